// round 13
// baseline (speedup 1.0000x reference)
#include <cuda_runtime.h>
#include <cuda_fp16.h>
#include <cstdint>

#define DIMV 1024
#define HEADS 16
#define HD 64
#define BATCH 4
#define SQ 1024
#define SKTOT 2048
#define KDIM 1024

// Scratch (allocation-free rule: __device__ globals)
__device__ __half g_Q[BATCH * HEADS * SQ * HD];
__device__ __half g_K[BATCH * HEADS * SKTOT * HD];
__device__ __half g_V[BATCH * HEADS * SKTOT * HD];
__device__ __half g_AO[BATCH * SQ * DIMV];
__device__ __half g_X[BATCH * SQ * DIMV];
__device__ __half g_Y[BATCH * SQ * DIMV];
__device__ __half g_W6[6 * DIMV * DIMV];

// ---------------- helpers ----------------
__device__ __forceinline__ uint32_t smem_u32(const void* p) {
    return (uint32_t)__cvta_generic_to_shared(p);
}
__device__ __forceinline__ void ldm_x4(uint32_t* r, uint32_t a) {
    asm volatile("ldmatrix.sync.aligned.m8n8.x4.shared.b16 {%0,%1,%2,%3}, [%4];"
                 : "=r"(r[0]), "=r"(r[1]), "=r"(r[2]), "=r"(r[3]) : "r"(a));
}
__device__ __forceinline__ void ldm_x4_t(uint32_t* r, uint32_t a) {
    asm volatile("ldmatrix.sync.aligned.m8n8.x4.trans.shared.b16 {%0,%1,%2,%3}, [%4];"
                 : "=r"(r[0]), "=r"(r[1]), "=r"(r[2]), "=r"(r[3]) : "r"(a));
}
__device__ __forceinline__ void mma_f16(float* c, const uint32_t* a, uint32_t b0, uint32_t b1) {
    asm volatile(
        "mma.sync.aligned.m16n8k16.row.col.f32.f16.f16.f32 "
        "{%0,%1,%2,%3},{%4,%5,%6,%7},{%8,%9},{%0,%1,%2,%3};"
        : "+f"(c[0]), "+f"(c[1]), "+f"(c[2]), "+f"(c[3])
        : "r"(a[0]), "r"(a[1]), "r"(a[2]), "r"(a[3]), "r"(b0), "r"(b1));
}
__device__ __forceinline__ uint32_t pack_h2(float a, float b) {
    __half2 h = __floats2half2_rn(a, b);
    return *(uint32_t*)&h;
}
#define CP16(dst, src) \
    asm volatile("cp.async.cg.shared.global [%0], [%1], 16;" :: "r"(dst), "l"(src))
#define CP_COMMIT() asm volatile("cp.async.commit_group;" ::)
#define CP_WAIT1()  asm volatile("cp.async.wait_group 1;" ::)
#define CP_WAIT0()  asm volatile("cp.async.wait_group 0;" ::)

// ---------------------------------------------------------------------------
// Pre-pass: fp32 -> fp16 conversion (x, y, 6 weight matrices)
// ---------------------------------------------------------------------------
struct RoundArgs { const float* src[8]; __half* dst[8]; int n4[8]; };

__global__ __launch_bounds__(256)
void to_half_k(RoundArgs ra) {
    int seg = blockIdx.y;
    const float4* s = (const float4*)ra.src[seg];
    __half2* d = (__half2*)ra.dst[seg];
    int n4 = ra.n4[seg];
    for (int i = blockIdx.x * blockDim.x + threadIdx.x; i < n4; i += gridDim.x * blockDim.x) {
        float4 v = s[i];
        d[2 * i + 0] = __floats2half2_rn(v.x, v.y);
        d[2 * i + 1] = __floats2half2_rn(v.z, v.w);
    }
}

// ---------------------------------------------------------------------------
// GEMM fp16: C[M,N] = A[M,1024] @ W[N,1024]^T + bias
// "Attention-shaped": CTA tile 64x128, 128 threads = 4 warps of 16x128.
// k-chunk 64, 2 smem stages (55.3KB) -> 4 CTAs/SM; ONE barrier per chunk,
// stage-after-barrier (buffer (c+1)&1 was consumed at c-1; barrier at top of
// c covers it -> race-free with 2 stages).
// ---------------------------------------------------------------------------
#define GKC 64                       // k-chunk (halves)
#define GST 72                       // smem row stride (halves, 144B)
#define A_STG (64 * GST)             // halves per A stage
#define W_STG (128 * GST)            // halves per W stage
#define GSMEM ((2 * A_STG + 2 * W_STG) * 2)   // 55,296 bytes

struct ProjArgs {
    const __half* A; const __half* W; const float* bias; void* out;
    int mode; int s_off;
};
struct Proj5 { ProjArgs p[5]; };

__device__ __forceinline__ void gemm_body(const __half* __restrict__ A,
                                          const __half* __restrict__ W,
                                          const float* __restrict__ bias,
                                          void* __restrict__ outp,
                                          int mode, int s_off)
{
    extern __shared__ __align__(16) __half dsm[];
    __half* As = dsm;                  // 2 stages of 64x72
    __half* Ws = dsm + 2 * A_STG;      // 2 stages of 128x72

    const int tid = threadIdx.x, lane = tid & 31, warp = tid >> 5;
    const int bm = blockIdx.y << 6, bn = blockIdx.x << 7;

    const __half* Ag = A + (size_t)bm * KDIM;
    const __half* Wg = W + (size_t)bn * KDIM;

    float acc[16][4];
#pragma unroll
    for (int j = 0; j < 16; j++)
#pragma unroll
        for (int v = 0; v < 4; v++) acc[j][v] = 0.f;

    const int a15 = lane & 15;
    const int hi8 = (lane >> 4) << 3;
    const int bg = (((lane >> 3) & 1) << 3) + (lane & 7);

    // stage chunk c into stage s: A 512 CP16 + W 1024 CP16, 12 per thread
#define STAGE_G(s, c) do { \
    _Pragma("unroll") \
    for (int j = 0; j < 4; j++) { \
        int ch = tid + 128 * j; \
        int row = ch >> 3, cp = ch & 7; \
        CP16(smem_u32(&As[(s) * A_STG + row * GST + cp * 8]), \
             (const char*)(Ag + (size_t)row * KDIM + (c) * GKC) + cp * 16); \
    } \
    _Pragma("unroll") \
    for (int j = 0; j < 8; j++) { \
        int ch = tid + 128 * j; \
        int row = ch >> 3, cp = ch & 7; \
        CP16(smem_u32(&Ws[(s) * W_STG + row * GST + cp * 8]), \
             (const char*)(Wg + (size_t)row * KDIM + (c) * GKC) + cp * 16); \
    } \
    CP_COMMIT(); \
} while (0)

    STAGE_G(0, 0);

    for (int c = 0; c < 16; c++) {
        CP_WAIT0();                 // chunk c resident (staged at iter c-1)
        __syncthreads();            // all warps done with iter c-1 -> safe to restage
        if (c + 1 < 16) STAGE_G((c + 1) & 1, c + 1);

        const __half* as = &As[(c & 1) * A_STG];
        const __half* ws = &Ws[(c & 1) * W_STG];
#pragma unroll
        for (int kk = 0; kk < GKC; kk += 16) {
            uint32_t af[4];
            ldm_x4(af, smem_u32(&as[(warp * 16 + a15) * GST + kk + hi8]));
#pragma unroll
            for (int nn = 0; nn < 8; nn++) {
                uint32_t r[4];
                ldm_x4(r, smem_u32(&ws[(nn * 16 + bg) * GST + kk + hi8]));
                mma_f16(acc[2 * nn], af, r[0], r[2]);
                mma_f16(acc[2 * nn + 1], af, r[1], r[3]);
            }
        }
    }

    const int r0 = lane >> 2, c2 = (lane & 3) << 1;
#pragma unroll
    for (int ni = 0; ni < 16; ni++) {
        int row0 = bm + warp * 16 + r0;
        int col = bn + ni * 8 + c2;
        float2 bv = *(const float2*)&bias[col];
        float v0 = acc[ni][0] + bv.x, v1 = acc[ni][1] + bv.y;
        float v2 = acc[ni][2] + bv.x, v3 = acc[ni][3] + bv.y;
        if (mode == 0) {
            float* o = (float*)outp;
            *(float2*)(o + (size_t)row0 * DIMV + col) = make_float2(v0, v1);
            *(float2*)(o + (size_t)(row0 + 8) * DIMV + col) = make_float2(v2, v3);
        } else {
            __half* o = (__half*)outp;
            int h = col >> 6, d = col & 63;
            int S = (mode == 1) ? SQ : SKTOT;
#pragma unroll
            for (int rr = 0; rr < 2; rr++) {
                int row = row0 + 8 * rr;
                int b = row >> 10, s = row & 1023;
                size_t idx = ((size_t)(b * HEADS + h) * S + (s + s_off)) * HD + d;
                __half2 hv = __floats2half2_rn(rr ? v2 : v0, rr ? v3 : v1);
                *(__half2*)(o + idx) = hv;
            }
        }
    }
}

__global__ __launch_bounds__(128, 4)
void proj5_h(Proj5 all) {
    ProjArgs a = all.p[blockIdx.z];
    gemm_body(a.A, a.W, a.bias, a.out, a.mode, a.s_off);
}
__global__ __launch_bounds__(128, 4)
void gemm1_h(ProjArgs a) {
    gemm_body(a.A, a.W, a.bias, a.out, a.mode, a.s_off);
}

// ---------------------------------------------------------------------------
// Flash attention fp16: 4 warps, q-tile 64 (16 rows/warp), k-tile 64, Dh=64.
// P register-direct into A-fragments. 3 K/V buffers, lookahead 1, single
// __syncthreads per tile.  (unchanged from R11)
// ---------------------------------------------------------------------------
#define HST 72
#define ATT_SMEM (6 * 64 * HST * 2)   // 3 K bufs + 3 V bufs

__global__ __launch_bounds__(128)
void attn_h(const __half* __restrict__ Q, const __half* __restrict__ K,
            const __half* __restrict__ V, __half* __restrict__ AO)
{
    extern __shared__ __align__(16) __half asm_[];
    __half* Kb[3], *Vb[3];
#pragma unroll
    for (int i = 0; i < 3; i++) {
        Kb[i] = asm_ + i * (64 * HST);
        Vb[i] = asm_ + (3 + i) * (64 * HST);
    }

    const int tid = threadIdx.x, lane = tid & 31, warp = tid >> 5;
    const int b = blockIdx.z, h = blockIdx.y, q0 = blockIdx.x * 64;

    const __half* Qg = Q + ((size_t)(b * HEADS + h) * SQ + q0) * HD;
    const __half* Kg = K + (size_t)(b * HEADS + h) * SKTOT * HD;
    const __half* Vg = V + (size_t)(b * HEADS + h) * SKTOT * HD;

    const int a15 = lane & 15;
    const int hi8 = (lane >> 4) << 3;
    const int bg = (((lane >> 3) & 1) << 3) + (lane & 7);
    const int r0 = lane >> 2, c2 = (lane & 3) << 1;

    // stage Q [64 x 64h] into Kb[0]
#pragma unroll
    for (int j = 0; j < 4; j++) {
        int ch = tid + 128 * j;            // 0..511
        int row = ch >> 3, cp = ch & 7;
        CP16(smem_u32(&Kb[0][row * HST + cp * 8]),
             (const char*)(Qg + (size_t)row * HD) + cp * 16);
    }
    CP_COMMIT(); CP_WAIT0();
    __syncthreads();

    uint32_t qf[4][4];
#pragma unroll
    for (int kf = 0; kf < 4; kf++)
        ldm_x4(qf[kf], smem_u32(&Kb[0][(warp * 16 + a15) * HST + kf * 16 + hi8]));
    __syncthreads();

#define STAGE_KV(buf, kt) do { \
    _Pragma("unroll") \
    for (int j = 0; j < 4; j++) { \
        int ch = tid + 128 * j; \
        int row = ch >> 3, cp = ch & 7; \
        CP16(smem_u32(&Kb[buf][row * HST + cp * 8]), \
             (const char*)(Kg + (size_t)((kt) + row) * HD) + cp * 16); \
        CP16(smem_u32(&Vb[buf][row * HST + cp * 8]), \
             (const char*)(Vg + (size_t)((kt) + row) * HD) + cp * 16); \
    } \
    CP_COMMIT(); \
} while (0)

    float O[8][4];
#pragma unroll
    for (int nf = 0; nf < 8; nf++)
#pragma unroll
        for (int v = 0; v < 4; v++) O[nf][v] = 0.f;
    float m0 = -1e30f, m1 = -1e30f, l0 = 0.f, l1 = 0.f;

    STAGE_KV(0, 0);

    int cb = 0, sb = 1;
    for (int t = 0; t < SKTOT / 64; t++) {
        if (t + 1 < SKTOT / 64) {
            STAGE_KV(sb, (t + 1) * 64);
            CP_WAIT1();
            sb = (sb == 2) ? 0 : sb + 1;
        } else {
            CP_WAIT0();
        }
        __syncthreads();

        const __half* ks = Kb[cb];
        const __half* vs = Vb[cb];
        cb = (cb == 2) ? 0 : cb + 1;

        // S = Q K^T : m16 x n64
        float s[8][4];
#pragma unroll
        for (int nf = 0; nf < 8; nf++)
#pragma unroll
            for (int v = 0; v < 4; v++) s[nf][v] = 0.f;
#pragma unroll
        for (int kf = 0; kf < 4; kf++) {
#pragma unroll
            for (int nn = 0; nn < 4; nn++) {
                uint32_t r[4];
                ldm_x4(r, smem_u32(&ks[(nn * 16 + bg) * HST + kf * 16 + hi8]));
                mma_f16(s[2 * nn], qf[kf], r[0], r[2]);
                mma_f16(s[2 * nn + 1], qf[kf], r[1], r[3]);
            }
        }

        // online softmax (scale 1/8 folded into exp args)
        float mx0 = fmaxf(s[0][0], s[0][1]), mx1 = fmaxf(s[0][2], s[0][3]);
#pragma unroll
        for (int nf = 1; nf < 8; nf++) {
            mx0 = fmaxf(mx0, fmaxf(s[nf][0], s[nf][1]));
            mx1 = fmaxf(mx1, fmaxf(s[nf][2], s[nf][3]));
        }
#pragma unroll
        for (int off = 1; off <= 2; off <<= 1) {
            mx0 = fmaxf(mx0, __shfl_xor_sync(0xffffffffu, mx0, off));
            mx1 = fmaxf(mx1, __shfl_xor_sync(0xffffffffu, mx1, off));
        }
        float nm0 = fmaxf(m0, mx0), nm1 = fmaxf(m1, mx1);
        float corr0 = __expf((m0 - nm0) * 0.125f);
        float corr1 = __expf((m1 - nm1) * 0.125f);
        m0 = nm0; m1 = nm1;

        uint32_t ph[8][2];
        float rs0 = 0.f, rs1 = 0.f;
#pragma unroll
        for (int nf = 0; nf < 8; nf++) {
            float p0 = __expf((s[nf][0] - nm0) * 0.125f);
            float p1 = __expf((s[nf][1] - nm0) * 0.125f);
            float p2 = __expf((s[nf][2] - nm1) * 0.125f);
            float p3 = __expf((s[nf][3] - nm1) * 0.125f);
            rs0 += p0 + p1; rs1 += p2 + p3;
            ph[nf][0] = pack_h2(p0, p1);
            ph[nf][1] = pack_h2(p2, p3);
        }
#pragma unroll
        for (int off = 1; off <= 2; off <<= 1) {
            rs0 += __shfl_xor_sync(0xffffffffu, rs0, off);
            rs1 += __shfl_xor_sync(0xffffffffu, rs1, off);
        }
        l0 = l0 * corr0 + rs0;
        l1 = l1 * corr1 + rs1;
#pragma unroll
        for (int nf = 0; nf < 8; nf++) {
            O[nf][0] *= corr0; O[nf][1] *= corr0;
            O[nf][2] *= corr1; O[nf][3] *= corr1;
        }

        // O += P V  (P A-frags from registers; V via ldmatrix.trans)
#pragma unroll
        for (int ks2 = 0; ks2 < 4; ks2++) {
            uint32_t af[4] = { ph[2 * ks2][0], ph[2 * ks2][1],
                               ph[2 * ks2 + 1][0], ph[2 * ks2 + 1][1] };
#pragma unroll
            for (int nn = 0; nn < 4; nn++) {
                uint32_t r[4];
                ldm_x4_t(r, smem_u32(&vs[(16 * ks2 + bg) * HST + nn * 16 + hi8]));
                mma_f16(O[2 * nn], af, r[0], r[1]);
                mma_f16(O[2 * nn + 1], af, r[2], r[3]);
            }
        }
    }

    float i0 = 1.f / l0, i1 = 1.f / l1;
    __half* out0 = AO + ((size_t)(b * SQ + q0 + warp * 16 + r0)) * DIMV + h * HD;
    __half* out1 = out0 + (size_t)8 * DIMV;
#pragma unroll
    for (int nf = 0; nf < 8; nf++) {
        *(__half2*)(out0 + nf * 8 + c2) = __floats2half2_rn(O[nf][0] * i0, O[nf][1] * i0);
        *(__half2*)(out1 + nf * 8 + c2) = __floats2half2_rn(O[nf][2] * i1, O[nf][3] * i1);
    }
}

// ---------------------------------------------------------------------------
extern "C" void kernel_launch(void* const* d_in, const int* in_sizes, int n_in,
                              void* d_out, int out_size)
{
    (void)in_sizes; (void)n_in; (void)out_size;
    const float* x     = (const float*)d_in[0];
    const float* y     = (const float*)d_in[1];
    const float* W_Kx  = (const float*)d_in[2];
    const float* b_Kx  = (const float*)d_in[3];
    const float* W_Qx  = (const float*)d_in[4];
    const float* b_Qx  = (const float*)d_in[5];
    const float* W_Vx  = (const float*)d_in[6];
    const float* b_Vx  = (const float*)d_in[7];
    const float* W_Ky  = (const float*)d_in[8];
    const float* b_Ky  = (const float*)d_in[9];
    const float* W_Vy  = (const float*)d_in[10];
    const float* b_Vy  = (const float*)d_in[11];
    const float* W_out = (const float*)d_in[12];
    const float* b_out = (const float*)d_in[13];
    float* out = (float*)d_out;

    void *pQ, *pK, *pV, *pAO, *pX, *pY, *pW;
    cudaGetSymbolAddress(&pQ, g_Q);
    cudaGetSymbolAddress(&pK, g_K);
    cudaGetSymbolAddress(&pV, g_V);
    cudaGetSymbolAddress(&pAO, g_AO);
    cudaGetSymbolAddress(&pX, g_X);
    cudaGetSymbolAddress(&pY, g_Y);
    cudaGetSymbolAddress(&pW, g_W6);
    __half* Qp  = (__half*)pQ;
    __half* Kp  = (__half*)pK;
    __half* Vp  = (__half*)pV;
    __half* AOp = (__half*)pAO;
    __half* Xp  = (__half*)pX;
    __half* Yp  = (__half*)pY;
    __half* Wp  = (__half*)pW;

    const int NW = DIMV * DIMV;
    const int NX = BATCH * SQ * DIMV;

    RoundArgs ra;
    ra.src[0] = x;     ra.dst[0] = Xp;          ra.n4[0] = NX / 4;
    ra.src[1] = y;     ra.dst[1] = Yp;          ra.n4[1] = NX / 4;
    ra.src[2] = W_Qx;  ra.dst[2] = Wp + 0 * NW; ra.n4[2] = NW / 4;
    ra.src[3] = W_Kx;  ra.dst[3] = Wp + 1 * NW; ra.n4[3] = NW / 4;
    ra.src[4] = W_Vx;  ra.dst[4] = Wp + 2 * NW; ra.n4[4] = NW / 4;
    ra.src[5] = W_Ky;  ra.dst[5] = Wp + 3 * NW; ra.n4[5] = NW / 4;
    ra.src[6] = W_Vy;  ra.dst[6] = Wp + 4 * NW; ra.n4[6] = NW / 4;
    ra.src[7] = W_out; ra.dst[7] = Wp + 5 * NW; ra.n4[7] = NW / 4;
    to_half_k<<<dim3(512, 8), 256>>>(ra);

    cudaFuncSetAttribute(proj5_h, cudaFuncAttributeMaxDynamicSharedMemorySize, GSMEM);
    cudaFuncSetAttribute(gemm1_h, cudaFuncAttributeMaxDynamicSharedMemorySize, GSMEM);
    cudaFuncSetAttribute(attn_h, cudaFuncAttributeMaxDynamicSharedMemorySize, ATT_SMEM);

    Proj5 pj;
    pj.p[0] = { Xp, Wp + 0 * NW, b_Qx, (void*)Qp, 1, 0 };
    pj.p[1] = { Xp, Wp + 1 * NW, b_Kx, (void*)Kp, 2, 0 };
    pj.p[2] = { Xp, Wp + 2 * NW, b_Vx, (void*)Vp, 2, 0 };
    pj.p[3] = { Yp, Wp + 3 * NW, b_Ky, (void*)Kp, 2, SQ };
    pj.p[4] = { Yp, Wp + 4 * NW, b_Vy, (void*)Vp, 2, SQ };

    proj5_h<<<dim3(8, 64, 5), 128, GSMEM>>>(pj);
    attn_h<<<dim3(SQ / 64, HEADS, BATCH), 128, ATT_SMEM>>>(Qp, Kp, Vp, AOp);
    gemm1_h<<<dim3(8, 64), 128, GSMEM>>>(ProjArgs{ AOp, Wp + 5 * NW, b_out, (void*)out, 0, 0 });
}

// round 15
// speedup vs baseline: 1.0505x; 1.0505x over previous
#include <cuda_runtime.h>
#include <cuda_fp16.h>
#include <cstdint>

#define DIMV 1024
#define HEADS 16
#define HD 64
#define BATCH 4
#define SQ 1024
#define SKTOT 2048
#define KDIM 1024

// Scratch (allocation-free rule: __device__ globals)
__device__ __half g_Q[BATCH * HEADS * SQ * HD];
__device__ __half g_K[BATCH * HEADS * SKTOT * HD];
__device__ __half g_V[BATCH * HEADS * SKTOT * HD];
__device__ __half g_AO[BATCH * SQ * DIMV];
__device__ __half g_X[BATCH * SQ * DIMV];
__device__ __half g_Y[BATCH * SQ * DIMV];
__device__ __half g_W6[6 * DIMV * DIMV];

// ---------------- helpers ----------------
__device__ __forceinline__ uint32_t smem_u32(const void* p) {
    return (uint32_t)__cvta_generic_to_shared(p);
}
__device__ __forceinline__ void ldm_x4(uint32_t* r, uint32_t a) {
    asm volatile("ldmatrix.sync.aligned.m8n8.x4.shared.b16 {%0,%1,%2,%3}, [%4];"
                 : "=r"(r[0]), "=r"(r[1]), "=r"(r[2]), "=r"(r[3]) : "r"(a));
}
__device__ __forceinline__ void ldm_x4_t(uint32_t* r, uint32_t a) {
    asm volatile("ldmatrix.sync.aligned.m8n8.x4.trans.shared.b16 {%0,%1,%2,%3}, [%4];"
                 : "=r"(r[0]), "=r"(r[1]), "=r"(r[2]), "=r"(r[3]) : "r"(a));
}
__device__ __forceinline__ void mma_f16(float* c, const uint32_t* a, uint32_t b0, uint32_t b1) {
    asm volatile(
        "mma.sync.aligned.m16n8k16.row.col.f32.f16.f16.f32 "
        "{%0,%1,%2,%3},{%4,%5,%6,%7},{%8,%9},{%0,%1,%2,%3};"
        : "+f"(c[0]), "+f"(c[1]), "+f"(c[2]), "+f"(c[3])
        : "r"(a[0]), "r"(a[1]), "r"(a[2]), "r"(a[3]), "r"(b0), "r"(b1));
}
__device__ __forceinline__ uint32_t pack_h2(float a, float b) {
    __half2 h = __floats2half2_rn(a, b);
    return *(uint32_t*)&h;
}
#define CP16(dst, src) \
    asm volatile("cp.async.cg.shared.global [%0], [%1], 16;" :: "r"(dst), "l"(src))
#define CP_COMMIT() asm volatile("cp.async.commit_group;" ::)
#define CP_WAIT1()  asm volatile("cp.async.wait_group 1;" ::)
#define CP_WAIT0()  asm volatile("cp.async.wait_group 0;" ::)

// ---------------------------------------------------------------------------
// Pre-pass: fp32 -> fp16 conversion (x, y, 6 weight matrices)
// ---------------------------------------------------------------------------
struct RoundArgs { const float* src[8]; __half* dst[8]; int n4[8]; };

__global__ __launch_bounds__(256)
void to_half_k(RoundArgs ra) {
    int seg = blockIdx.y;
    const float4* s = (const float4*)ra.src[seg];
    __half2* d = (__half2*)ra.dst[seg];
    int n4 = ra.n4[seg];
    for (int i = blockIdx.x * blockDim.x + threadIdx.x; i < n4; i += gridDim.x * blockDim.x) {
        float4 v = s[i];
        d[2 * i + 0] = __floats2half2_rn(v.x, v.y);
        d[2 * i + 1] = __floats2half2_rn(v.z, v.w);
    }
}

// ---------------------------------------------------------------------------
// GEMM fp16: C[M,N] = A[M,1024] @ W[N,1024]^T + bias
// CTA tile 64x128, 128 threads = 4 warps of 32x64 (R11 warp shape/inner loop).
// k-chunk 64, 2 smem stages (55.3KB) -> 4 CTAs/SM, ~120 regs.
// ONE barrier per chunk; stage next chunk after barrier (in flight during mma).
// ---------------------------------------------------------------------------
#define GKC 64                       // k-chunk (halves)
#define GST 72                       // smem row stride (halves, 144B)
#define A_STG (64 * GST)             // halves per A stage
#define W_STG (128 * GST)            // halves per W stage
#define GSMEM ((2 * A_STG + 2 * W_STG) * 2)   // 55,296 bytes

struct ProjArgs {
    const __half* A; const __half* W; const float* bias; void* out;
    int mode; int s_off;
};
struct Proj5 { ProjArgs p[5]; };

__device__ __forceinline__ void gemm_body(const __half* __restrict__ A,
                                          const __half* __restrict__ W,
                                          const float* __restrict__ bias,
                                          void* __restrict__ outp,
                                          int mode, int s_off)
{
    extern __shared__ __align__(16) __half dsm[];
    __half* As = dsm;                  // 2 stages of 64x72
    __half* Ws = dsm + 2 * A_STG;      // 2 stages of 128x72

    const int tid = threadIdx.x, lane = tid & 31, warp = tid >> 5;
    const int wm = (warp >> 1) << 5, wn = (warp & 1) << 6;   // 2x2 warps of 32x64
    const int bm = blockIdx.y << 6, bn = blockIdx.x << 7;

    const __half* Ag = A + (size_t)bm * KDIM;
    const __half* Wg = W + (size_t)bn * KDIM;

    float acc[2][8][4];
#pragma unroll
    for (int i = 0; i < 2; i++)
#pragma unroll
        for (int j = 0; j < 8; j++)
#pragma unroll
            for (int v = 0; v < 4; v++) acc[i][j][v] = 0.f;

    const int a15 = lane & 15;
    const int hi8 = (lane >> 4) << 3;
    const int bg = (((lane >> 3) & 1) << 3) + (lane & 7);

    // stage chunk c into stage s: A 512 CP16 + W 1024 CP16, 12 per thread
#define STAGE_G(s, c) do { \
    _Pragma("unroll") \
    for (int j = 0; j < 4; j++) { \
        int ch = tid + 128 * j; \
        int row = ch >> 3, cp = ch & 7; \
        CP16(smem_u32(&As[(s) * A_STG + row * GST + cp * 8]), \
             (const char*)(Ag + (size_t)row * KDIM + (c) * GKC) + cp * 16); \
    } \
    _Pragma("unroll") \
    for (int j = 0; j < 8; j++) { \
        int ch = tid + 128 * j; \
        int row = ch >> 3, cp = ch & 7; \
        CP16(smem_u32(&Ws[(s) * W_STG + row * GST + cp * 8]), \
             (const char*)(Wg + (size_t)row * KDIM + (c) * GKC) + cp * 16); \
    } \
    CP_COMMIT(); \
} while (0)

    STAGE_G(0, 0);

    for (int c = 0; c < 16; c++) {
        CP_WAIT0();                 // chunk c resident (staged at iter c-1)
        __syncthreads();            // all warps done with iter c-1 -> restage safe
        if (c + 1 < 16) STAGE_G((c + 1) & 1, c + 1);

        const __half* as = &As[(c & 1) * A_STG];
        const __half* ws = &Ws[(c & 1) * W_STG];
#pragma unroll
        for (int kk = 0; kk < GKC; kk += 16) {
            uint32_t af[2][4];
#pragma unroll
            for (int mi = 0; mi < 2; mi++)
                ldm_x4(af[mi], smem_u32(&as[(wm + mi * 16 + a15) * GST + kk + hi8]));
            uint32_t bf[8][2];
#pragma unroll
            for (int nn = 0; nn < 4; nn++) {
                uint32_t r[4];
                ldm_x4(r, smem_u32(&ws[(wn + nn * 16 + bg) * GST + kk + hi8]));
                bf[2 * nn][0] = r[0]; bf[2 * nn][1] = r[2];
                bf[2 * nn + 1][0] = r[1]; bf[2 * nn + 1][1] = r[3];
            }
#pragma unroll
            for (int mi = 0; mi < 2; mi++)
#pragma unroll
                for (int ni = 0; ni < 8; ni++)
                    mma_f16(acc[mi][ni], af[mi], bf[ni][0], bf[ni][1]);
        }
    }

    const int r0 = lane >> 2, c2 = (lane & 3) << 1;
#pragma unroll
    for (int mi = 0; mi < 2; mi++) {
        int row0 = bm + wm + mi * 16 + r0;
#pragma unroll
        for (int ni = 0; ni < 8; ni++) {
            int col = bn + wn + ni * 8 + c2;
            float2 bv = *(const float2*)&bias[col];
            float v0 = acc[mi][ni][0] + bv.x, v1 = acc[mi][ni][1] + bv.y;
            float v2 = acc[mi][ni][2] + bv.x, v3 = acc[mi][ni][3] + bv.y;
            if (mode == 0) {
                float* o = (float*)outp;
                *(float2*)(o + (size_t)row0 * DIMV + col) = make_float2(v0, v1);
                *(float2*)(o + (size_t)(row0 + 8) * DIMV + col) = make_float2(v2, v3);
            } else {
                __half* o = (__half*)outp;
                int h = col >> 6, d = col & 63;
                int S = (mode == 1) ? SQ : SKTOT;
#pragma unroll
                for (int rr = 0; rr < 2; rr++) {
                    int row = row0 + 8 * rr;
                    int b = row >> 10, s = row & 1023;
                    size_t idx = ((size_t)(b * HEADS + h) * S + (s + s_off)) * HD + d;
                    __half2 hv = __floats2half2_rn(rr ? v2 : v0, rr ? v3 : v1);
                    *(__half2*)(o + idx) = hv;
                }
            }
        }
    }
}

__global__ __launch_bounds__(128, 4)
void proj5_h(Proj5 all) {
    ProjArgs a = all.p[blockIdx.z];
    gemm_body(a.A, a.W, a.bias, a.out, a.mode, a.s_off);
}
__global__ __launch_bounds__(128, 4)
void gemm1_h(ProjArgs a) {
    gemm_body(a.A, a.W, a.bias, a.out, a.mode, a.s_off);
}

// ---------------------------------------------------------------------------
// Flash attention fp16: 4 warps, q-tile 64 (16 rows/warp), k-tile 64, Dh=64.
// P register-direct into A-fragments. 3 K/V buffers, lookahead 1, single
// __syncthreads per tile.  (unchanged from R11)
// ---------------------------------------------------------------------------
#define HST 72
#define ATT_SMEM (6 * 64 * HST * 2)   // 3 K bufs + 3 V bufs

__global__ __launch_bounds__(128)
void attn_h(const __half* __restrict__ Q, const __half* __restrict__ K,
            const __half* __restrict__ V, __half* __restrict__ AO)
{
    extern __shared__ __align__(16) __half asm_[];
    __half* Kb[3], *Vb[3];
#pragma unroll
    for (int i = 0; i < 3; i++) {
        Kb[i] = asm_ + i * (64 * HST);
        Vb[i] = asm_ + (3 + i) * (64 * HST);
    }

    const int tid = threadIdx.x, lane = tid & 31, warp = tid >> 5;
    const int b = blockIdx.z, h = blockIdx.y, q0 = blockIdx.x * 64;

    const __half* Qg = Q + ((size_t)(b * HEADS + h) * SQ + q0) * HD;
    const __half* Kg = K + (size_t)(b * HEADS + h) * SKTOT * HD;
    const __half* Vg = V + (size_t)(b * HEADS + h) * SKTOT * HD;

    const int a15 = lane & 15;
    const int hi8 = (lane >> 4) << 3;
    const int bg = (((lane >> 3) & 1) << 3) + (lane & 7);
    const int r0 = lane >> 2, c2 = (lane & 3) << 1;

    // stage Q [64 x 64h] into Kb[0]
#pragma unroll
    for (int j = 0; j < 4; j++) {
        int ch = tid + 128 * j;            // 0..511
        int row = ch >> 3, cp = ch & 7;
        CP16(smem_u32(&Kb[0][row * HST + cp * 8]),
             (const char*)(Qg + (size_t)row * HD) + cp * 16);
    }
    CP_COMMIT(); CP_WAIT0();
    __syncthreads();

    uint32_t qf[4][4];
#pragma unroll
    for (int kf = 0; kf < 4; kf++)
        ldm_x4(qf[kf], smem_u32(&Kb[0][(warp * 16 + a15) * HST + kf * 16 + hi8]));
    __syncthreads();

#define STAGE_KV(buf, kt) do { \
    _Pragma("unroll") \
    for (int j = 0; j < 4; j++) { \
        int ch = tid + 128 * j; \
        int row = ch >> 3, cp = ch & 7; \
        CP16(smem_u32(&Kb[buf][row * HST + cp * 8]), \
             (const char*)(Kg + (size_t)((kt) + row) * HD) + cp * 16); \
        CP16(smem_u32(&Vb[buf][row * HST + cp * 8]), \
             (const char*)(Vg + (size_t)((kt) + row) * HD) + cp * 16); \
    } \
    CP_COMMIT(); \
} while (0)

    float O[8][4];
#pragma unroll
    for (int nf = 0; nf < 8; nf++)
#pragma unroll
        for (int v = 0; v < 4; v++) O[nf][v] = 0.f;
    float m0 = -1e30f, m1 = -1e30f, l0 = 0.f, l1 = 0.f;

    STAGE_KV(0, 0);

    int cb = 0, sb = 1;
    for (int t = 0; t < SKTOT / 64; t++) {
        if (t + 1 < SKTOT / 64) {
            STAGE_KV(sb, (t + 1) * 64);
            CP_WAIT1();
            sb = (sb == 2) ? 0 : sb + 1;
        } else {
            CP_WAIT0();
        }
        __syncthreads();

        const __half* ks = Kb[cb];
        const __half* vs = Vb[cb];
        cb = (cb == 2) ? 0 : cb + 1;

        // S = Q K^T : m16 x n64
        float s[8][4];
#pragma unroll
        for (int nf = 0; nf < 8; nf++)
#pragma unroll
            for (int v = 0; v < 4; v++) s[nf][v] = 0.f;
#pragma unroll
        for (int kf = 0; kf < 4; kf++) {
#pragma unroll
            for (int nn = 0; nn < 4; nn++) {
                uint32_t r[4];
                ldm_x4(r, smem_u32(&ks[(nn * 16 + bg) * HST + kf * 16 + hi8]));
                mma_f16(s[2 * nn], qf[kf], r[0], r[2]);
                mma_f16(s[2 * nn + 1], qf[kf], r[1], r[3]);
            }
        }

        // online softmax (scale 1/8 folded into exp args)
        float mx0 = fmaxf(s[0][0], s[0][1]), mx1 = fmaxf(s[0][2], s[0][3]);
#pragma unroll
        for (int nf = 1; nf < 8; nf++) {
            mx0 = fmaxf(mx0, fmaxf(s[nf][0], s[nf][1]));
            mx1 = fmaxf(mx1, fmaxf(s[nf][2], s[nf][3]));
        }
#pragma unroll
        for (int off = 1; off <= 2; off <<= 1) {
            mx0 = fmaxf(mx0, __shfl_xor_sync(0xffffffffu, mx0, off));
            mx1 = fmaxf(mx1, __shfl_xor_sync(0xffffffffu, mx1, off));
        }
        float nm0 = fmaxf(m0, mx0), nm1 = fmaxf(m1, mx1);
        float corr0 = __expf((m0 - nm0) * 0.125f);
        float corr1 = __expf((m1 - nm1) * 0.125f);
        m0 = nm0; m1 = nm1;

        uint32_t ph[8][2];
        float rs0 = 0.f, rs1 = 0.f;
#pragma unroll
        for (int nf = 0; nf < 8; nf++) {
            float p0 = __expf((s[nf][0] - nm0) * 0.125f);
            float p1 = __expf((s[nf][1] - nm0) * 0.125f);
            float p2 = __expf((s[nf][2] - nm1) * 0.125f);
            float p3 = __expf((s[nf][3] - nm1) * 0.125f);
            rs0 += p0 + p1; rs1 += p2 + p3;
            ph[nf][0] = pack_h2(p0, p1);
            ph[nf][1] = pack_h2(p2, p3);
        }
#pragma unroll
        for (int off = 1; off <= 2; off <<= 1) {
            rs0 += __shfl_xor_sync(0xffffffffu, rs0, off);
            rs1 += __shfl_xor_sync(0xffffffffu, rs1, off);
        }
        l0 = l0 * corr0 + rs0;
        l1 = l1 * corr1 + rs1;
#pragma unroll
        for (int nf = 0; nf < 8; nf++) {
            O[nf][0] *= corr0; O[nf][1] *= corr0;
            O[nf][2] *= corr1; O[nf][3] *= corr1;
        }

        // O += P V  (P A-frags from registers; V via ldmatrix.trans)
#pragma unroll
        for (int ks2 = 0; ks2 < 4; ks2++) {
            uint32_t af[4] = { ph[2 * ks2][0], ph[2 * ks2][1],
                               ph[2 * ks2 + 1][0], ph[2 * ks2 + 1][1] };
#pragma unroll
            for (int nn = 0; nn < 4; nn++) {
                uint32_t r[4];
                ldm_x4_t(r, smem_u32(&vs[(16 * ks2 + bg) * HST + nn * 16 + hi8]));
                mma_f16(O[2 * nn], af, r[0], r[1]);
                mma_f16(O[2 * nn + 1], af, r[2], r[3]);
            }
        }
    }

    float i0 = 1.f / l0, i1 = 1.f / l1;
    __half* out0 = AO + ((size_t)(b * SQ + q0 + warp * 16 + r0)) * DIMV + h * HD;
    __half* out1 = out0 + (size_t)8 * DIMV;
#pragma unroll
    for (int nf = 0; nf < 8; nf++) {
        *(__half2*)(out0 + nf * 8 + c2) = __floats2half2_rn(O[nf][0] * i0, O[nf][1] * i0);
        *(__half2*)(out1 + nf * 8 + c2) = __floats2half2_rn(O[nf][2] * i1, O[nf][3] * i1);
    }
}

// ---------------------------------------------------------------------------
extern "C" void kernel_launch(void* const* d_in, const int* in_sizes, int n_in,
                              void* d_out, int out_size)
{
    (void)in_sizes; (void)n_in; (void)out_size;
    const float* x     = (const float*)d_in[0];
    const float* y     = (const float*)d_in[1];
    const float* W_Kx  = (const float*)d_in[2];
    const float* b_Kx  = (const float*)d_in[3];
    const float* W_Qx  = (const float*)d_in[4];
    const float* b_Qx  = (const float*)d_in[5];
    const float* W_Vx  = (const float*)d_in[6];
    const float* b_Vx  = (const float*)d_in[7];
    const float* W_Ky  = (const float*)d_in[8];
    const float* b_Ky  = (const float*)d_in[9];
    const float* W_Vy  = (const float*)d_in[10];
    const float* b_Vy  = (const float*)d_in[11];
    const float* W_out = (const float*)d_in[12];
    const float* b_out = (const float*)d_in[13];
    float* out = (float*)d_out;

    void *pQ, *pK, *pV, *pAO, *pX, *pY, *pW;
    cudaGetSymbolAddress(&pQ, g_Q);
    cudaGetSymbolAddress(&pK, g_K);
    cudaGetSymbolAddress(&pV, g_V);
    cudaGetSymbolAddress(&pAO, g_AO);
    cudaGetSymbolAddress(&pX, g_X);
    cudaGetSymbolAddress(&pY, g_Y);
    cudaGetSymbolAddress(&pW, g_W6);
    __half* Qp  = (__half*)pQ;
    __half* Kp  = (__half*)pK;
    __half* Vp  = (__half*)pV;
    __half* AOp = (__half*)pAO;
    __half* Xp  = (__half*)pX;
    __half* Yp  = (__half*)pY;
    __half* Wp  = (__half*)pW;

    const int NW = DIMV * DIMV;
    const int NX = BATCH * SQ * DIMV;

    RoundArgs ra;
    ra.src[0] = x;     ra.dst[0] = Xp;          ra.n4[0] = NX / 4;
    ra.src[1] = y;     ra.dst[1] = Yp;          ra.n4[1] = NX / 4;
    ra.src[2] = W_Qx;  ra.dst[2] = Wp + 0 * NW; ra.n4[2] = NW / 4;
    ra.src[3] = W_Kx;  ra.dst[3] = Wp + 1 * NW; ra.n4[3] = NW / 4;
    ra.src[4] = W_Vx;  ra.dst[4] = Wp + 2 * NW; ra.n4[4] = NW / 4;
    ra.src[5] = W_Ky;  ra.dst[5] = Wp + 3 * NW; ra.n4[5] = NW / 4;
    ra.src[6] = W_Vy;  ra.dst[6] = Wp + 4 * NW; ra.n4[6] = NW / 4;
    ra.src[7] = W_out; ra.dst[7] = Wp + 5 * NW; ra.n4[7] = NW / 4;
    to_half_k<<<dim3(512, 8), 256>>>(ra);

    cudaFuncSetAttribute(proj5_h, cudaFuncAttributeMaxDynamicSharedMemorySize, GSMEM);
    cudaFuncSetAttribute(gemm1_h, cudaFuncAttributeMaxDynamicSharedMemorySize, GSMEM);
    cudaFuncSetAttribute(attn_h, cudaFuncAttributeMaxDynamicSharedMemorySize, ATT_SMEM);

    Proj5 pj;
    pj.p[0] = { Xp, Wp + 0 * NW, b_Qx, (void*)Qp, 1, 0 };
    pj.p[1] = { Xp, Wp + 1 * NW, b_Kx, (void*)Kp, 2, 0 };
    pj.p[2] = { Xp, Wp + 2 * NW, b_Vx, (void*)Vp, 2, 0 };
    pj.p[3] = { Yp, Wp + 3 * NW, b_Ky, (void*)Kp, 2, SQ };
    pj.p[4] = { Yp, Wp + 4 * NW, b_Vy, (void*)Vp, 2, SQ };

    proj5_h<<<dim3(8, 64, 5), 128, GSMEM>>>(pj);
    attn_h<<<dim3(SQ / 64, HEADS, BATCH), 128, ATT_SMEM>>>(Qp, Kp, Vp, AOp);
    gemm1_h<<<dim3(8, 64), 128, GSMEM>>>(ProjArgs{ AOp, Wp + 5 * NW, b_out, (void*)out, 0, 0 });
}